// round 6
// baseline (speedup 1.0000x reference)
#include <cuda_runtime.h>
#include <cuda_fp16.h>
#include <cstdint>

// ============================================================
// TopKRouter, warp-specialized HMMA fp16 2-split pipeline:
//   logits = x @ W^T + b ; top-2 ; softmax(top2)
// x:[16384,2048] f32  W:[64,2048] f32  b:[64] f32
// out: [n*2] gates f32, then [n*2] indices as f32
// warps 0-3: MMA consumers; warps 4-7: producers (LDG/convert/cp.async)
// ============================================================

#define D_DIM  2048
#define NEXP   64
#define M_CTA  64
#define NCH    32           // k-chunks of 64
#define NSTG   3            // pipeline stages
#define NTHREADS 256

// smem: [0,256) bias | [256,352) mbarriers | [1024,...) 3 stages x 32KB
#define STG(s)   (1024 + (s) * 32768)
#define ABYTES   8192
#define SMEM_TOTAL (1024 + NSTG * 32768)   // 99328
#define LG_OFF   1024
#define LGS      65
#define SW16(row, c) ((row) * 128 + ((((c) ^ ((row) & 7))) << 4))

// W fp16 splits: w0 = fp16(w), w1 = fp16((w - w0) * 2048)
__device__ __align__(16) __half w0g[NEXP * D_DIM];
__device__ __align__(16) __half w1g[NEXP * D_DIM];

__global__ void wconv(const float* __restrict__ W) {
    int i = blockIdx.x * blockDim.x + threadIdx.x;
    float w = W[i];
    __half h0 = __float2half_rn(w);
    float  r  = w - __half2float(h0);
    w0g[i] = h0;
    w1g[i] = __float2half_rn(r * 2048.0f);
}

// ---------------- asm helpers ----------------
__device__ __forceinline__ uint32_t smem_u32(const void* p) {
    uint32_t a;
    asm("{ .reg .u64 t; cvta.to.shared.u64 t, %1; cvt.u32.u64 %0, t; }"
        : "=r"(a) : "l"(p));
    return a;
}
__device__ __forceinline__ void ldsm4(uint32_t* r, uint32_t addr) {
    asm volatile("ldmatrix.sync.aligned.m8n8.x4.shared.b16 {%0,%1,%2,%3}, [%4];"
                 : "=r"(r[0]), "=r"(r[1]), "=r"(r[2]), "=r"(r[3]) : "r"(addr));
}
__device__ __forceinline__ void mma16816(float* d, const uint32_t* a, const uint32_t* b) {
    asm volatile("mma.sync.aligned.m16n8k16.row.col.f32.f16.f16.f32 "
                 "{%0,%1,%2,%3}, {%4,%5,%6,%7}, {%8,%9}, {%0,%1,%2,%3};"
                 : "+f"(d[0]), "+f"(d[1]), "+f"(d[2]), "+f"(d[3])
                 : "r"(a[0]), "r"(a[1]), "r"(a[2]), "r"(a[3]), "r"(b[0]), "r"(b[1]));
}
__device__ __forceinline__ void cp16(uint32_t saddr, const void* gaddr) {
    asm volatile("cp.async.cg.shared.global [%0], [%1], 16;" :: "r"(saddr), "l"(gaddr));
}
#define MBAR_INIT(a, c) \
    asm volatile("mbarrier.init.shared.b64 [%0], %1;" :: "r"(a), "r"(c) : "memory")
#define MBAR_ARRIVE(a) \
    asm volatile("mbarrier.arrive.shared.b64 _, [%0];" :: "r"(a) : "memory")
// .noinc is load-bearing: default variant raises pend-count by 1 per thread
// (net-zero arrivals) and deadlocks a pre-armed barrier.
#define CP_MBAR_ARRIVE(a) \
    asm volatile("cp.async.mbarrier.arrive.noinc.shared.b64 [%0];" :: "r"(a) : "memory")
#define MBAR_WAIT(addr, ph) do { \
    asm volatile("{\n\t.reg .pred P;\n\tWLP_%=:\n\t" \
        "mbarrier.try_wait.parity.acquire.cta.shared::cta.b64 P, [%0], %1, 0x989680;\n\t" \
        "@!P bra WLP_%=;\n\t}" :: "r"(addr), "r"(ph) : "memory"); \
} while (0)
#define STS128(addr, v) \
    asm volatile("st.shared.v4.b32 [%0], {%1,%2,%3,%4};" \
                 :: "r"(addr), "r"((v).x), "r"((v).y), "r"((v).z), "r"((v).w) : "memory")

__device__ __forceinline__ uint32_t cvt2(float u, float v, uint32_t& h1) {
    __half2 a = __float22half2_rn(make_float2(u, v));
    float2 f  = __half22float2(a);
    __half2 r = __float22half2_rn(make_float2(u - f.x, v - f.y));
    h1 = *reinterpret_cast<uint32_t*>(&r);
    return *reinterpret_cast<uint32_t*>(&a);
}

// ---------------- main kernel ----------------
__global__ __launch_bounds__(NTHREADS, 2)
void router_main(const float* __restrict__ x, const float* __restrict__ b,
                 float* __restrict__ out, int n_tokens)
{
    extern __shared__ __align__(1024) char smem[];
    const uint32_t sb = smem_u32(smem);
    const int tid  = threadIdx.x;
    const int lane = tid & 31;
    const int tok0 = blockIdx.x * M_CTA;

    // mbarriers: full[s] = sb+256+s*16, empty[s] = +8
    if (tid == 0) {
#pragma unroll
        for (int s = 0; s < NSTG; s++) {
            MBAR_INIT(sb + 256 + s * 16, 256);      // full: 128 STS + 128 cp arrivals
            MBAR_INIT(sb + 256 + s * 16 + 8, 128);  // empty: 128 consumer arrivals
        }
    }
    if (tid < NEXP) reinterpret_cast<float*>(smem)[tid] = b[tid];
    __syncthreads();

    if (tid >= 128) {
        // ================= PRODUCER =================
        const int pt   = tid - 128;
        const int row  = pt >> 1;         // 0..63 (token row AND expert row)
        const int half = pt & 1;
        const float4* xp = reinterpret_cast<const float4*>(x)
                           + (size_t)(tok0 + row) * (D_DIM / 4) + half * 8;
        const char* wg = reinterpret_cast<const char*>(half ? w1g : w0g)
                         + row * (D_DIM * 2);
        const uint32_t wdst_off = 16384 + half * 8192;

        uint32_t asw[4], wsw[8];
#pragma unroll
        for (int q = 0; q < 4; q++) asw[q] = SW16(row, half * 4 + q);
#pragma unroll
        for (int c = 0; c < 8; c++) wsw[c] = SW16(row, c);

        float4 xv[8];
#pragma unroll
        for (int i = 0; i < 8; i++) xv[i] = xp[i];

        int s = 0, ph = 1;
        for (int ch = 0; ch < NCH; ch++) {
            const uint32_t fullb  = sb + 256 + s * 16;
            const uint32_t emptyb = fullb + 8;
            MBAR_WAIT(emptyb, ph);
            const uint32_t stg = sb + STG(s);

            // W chunk via cp.async FIRST (independent of conversions)
#pragma unroll
            for (int c = 0; c < 8; c++)
                cp16(stg + wdst_off + wsw[c], wg + ch * 128 + c * 16);

            // x split -> STS.128 x4 (h0) + x4 (h1)
#pragma unroll
            for (int q = 0; q < 4; q++) {
                float4 a = xv[2 * q], c = xv[2 * q + 1];
                uint4 h0q, h1q;
                h0q.x = cvt2(a.x, a.y, h1q.x);
                h0q.y = cvt2(a.z, a.w, h1q.y);
                h0q.z = cvt2(c.x, c.y, h1q.z);
                h0q.w = cvt2(c.z, c.w, h1q.w);
                STS128(stg + asw[q], h0q);
                STS128(stg + ABYTES + asw[q], h1q);
            }
            CP_MBAR_ARRIVE(fullb);
            MBAR_ARRIVE(fullb);

            // prefetch next x chunk
            if (ch + 1 < NCH) {
#pragma unroll
                for (int i = 0; i < 8; i++) xv[i] = xp[(ch + 1) * 16 + i];
            }
            if (++s == NSTG) { s = 0; ph ^= 1; }
        }
        return;   // producers done
    }

    // ================= CONSUMER (warps 0-3) =================
    const int wid = tid >> 5;
    const int m0  = (wid & 1) * 32;
    const int n0  = (wid >> 1) * 32;

    float acc0[2][4][4], acc1[2][4][4];
#pragma unroll
    for (int mi = 0; mi < 2; mi++)
#pragma unroll
        for (int ng = 0; ng < 4; ng++)
#pragma unroll
            for (int q = 0; q < 4; q++) { acc0[mi][ng][q] = 0.f; acc1[mi][ng][q] = 0.f; }

    const int rowA  = m0 + (lane & 15);
    const int cAoff = lane >> 4;
    const int rowB  = n0 + (lane & 7) + ((lane >> 4) << 3);
    const int cBoff = (lane >> 3) & 1;

    int s = 0, ph = 0;
    for (int ch = 0; ch < NCH; ch++) {
        const uint32_t fullb  = sb + 256 + s * 16;
        const uint32_t emptyb = fullb + 8;
        MBAR_WAIT(fullb, ph);
        const uint32_t stg = sb + STG(s);

#pragma unroll
        for (int kk = 0; kk < 4; kk++) {
            uint32_t a0f[2][4], a1f[2][4], b0f[2][4], b1f[2][4];
            const int cA = kk * 2 + cAoff;
            const int cB = kk * 2 + cBoff;
#pragma unroll
            for (int mi = 0; mi < 2; mi++) {
                uint32_t ad = stg + SW16(rowA + mi * 16, cA);
                ldsm4(a0f[mi], ad);
                ldsm4(a1f[mi], ad + ABYTES);
            }
#pragma unroll
            for (int ni2 = 0; ni2 < 2; ni2++) {
                uint32_t bd = stg + 16384 + SW16(rowB + ni2 * 16, cB);
                ldsm4(b0f[ni2], bd);
                ldsm4(b1f[ni2], bd + ABYTES);
            }
#pragma unroll
            for (int mi = 0; mi < 2; mi++) {
#pragma unroll
                for (int ng = 0; ng < 4; ng++) {
                    const uint32_t* B0 = &b0f[ng >> 1][(ng & 1) * 2];
                    const uint32_t* B1 = &b1f[ng >> 1][(ng & 1) * 2];
                    mma16816(acc0[mi][ng], a0f[mi], B0);
                    mma16816(acc0[mi][ng], a1f[mi], B0);
                    mma16816(acc1[mi][ng], a0f[mi], B1);
                }
            }
        }
        MBAR_ARRIVE(emptyb);
        if (++s == NSTG) { s = 0; ph ^= 1; }
    }

    // All consumer warps must be done READING stage 0 before anyone
    // overwrites it with logits (lg aliases STG(0)); warps can skew by
    // several chunks, so sync consumers FIRST.  (R5 bug: this barrier
    // was after the writes -> stage-0 read/write race.)
    asm volatile("bar.sync 1, 128;" ::: "memory");

    // ---- epilogue: combine splits -> logits smem ----
    float* lg = reinterpret_cast<float*>(smem + LG_OFF);
    const float S = 4.8828125e-4f;  // 2^-11
#pragma unroll
    for (int mi = 0; mi < 2; mi++) {
#pragma unroll
        for (int ng = 0; ng < 4; ng++) {
            int row = m0 + mi * 16 + (lane >> 2);
            int col = n0 + ng * 8 + 2 * (lane & 3);
            lg[row * LGS + col]           = acc0[mi][ng][0] + S * acc1[mi][ng][0];
            lg[row * LGS + col + 1]       = acc0[mi][ng][1] + S * acc1[mi][ng][1];
            lg[(row + 8) * LGS + col]     = acc0[mi][ng][2] + S * acc1[mi][ng][2];
            lg[(row + 8) * LGS + col + 1] = acc0[mi][ng][3] + S * acc1[mi][ng][3];
        }
    }
    asm volatile("bar.sync 1, 128;" ::: "memory");

    // ---- top-2 + softmax, one thread per token ----
    if (tid < M_CTA) {
        const float* row = &lg[tid * LGS];
        const float* bs  = reinterpret_cast<const float*>(smem);
        float v1 = -3.402823466e+38f, v2 = -3.402823466e+38f;
        int i1 = 0, i2 = 0;
#pragma unroll
        for (int e = 0; e < NEXP; e++) {
            float v = row[e] + bs[e];
            if (v > v1)      { v2 = v1; i2 = i1; v1 = v; i1 = e; }
            else if (v > v2) { v2 = v;  i2 = e; }
        }
        float e2  = expf(v2 - v1);
        float inv = 1.0f / (1.0f + e2);
        const int g = tok0 + tid;
        out[2 * g + 0] = inv;
        out[2 * g + 1] = e2 * inv;
        out[2 * n_tokens + 2 * g + 0] = (float)i1;
        out[2 * n_tokens + 2 * g + 1] = (float)i2;
    }
}

// ---------------- launch ----------------
extern "C" void kernel_launch(void* const* d_in, const int* in_sizes, int n_in,
                              void* d_out, int out_size)
{
    const float* x = (const float*)d_in[0];
    const float* W = (const float*)d_in[1];
    const float* b = (const float*)d_in[2];
    float* out = (float*)d_out;

    const int n_tokens = in_sizes[0] / D_DIM;   // 16384
    const int grid = n_tokens / M_CTA;          // 256

    cudaFuncSetAttribute(router_main, cudaFuncAttributeMaxDynamicSharedMemorySize, SMEM_TOTAL);

    wconv<<<NEXP * D_DIM / 256, 256>>>(W);
    router_main<<<grid, NTHREADS, SMEM_TOTAL>>>(x, b, out, n_tokens);
}

// round 7
// speedup vs baseline: 1.1409x; 1.1409x over previous
#include <cuda_runtime.h>
#include <cuda_fp16.h>
#include <cstdint>

// ============================================================
// TopKRouter, warp-specialized HMMA fp16 2-split pipeline v2:
//   logits = x @ W^T + b ; top-2 ; softmax(top2)
// One CTA per SM: M_CTA=128, 384 threads.
//   warps 0-7 : MMA consumers (32x32 tiles)
//   warps 8-11: producers (x LDG+split+STS, W cp.async)
// 4-stage smem ring, mbarrier protocol.
// out: [n*2] gates f32, then [n*2] indices as f32
// ============================================================

#define D_DIM  2048
#define NEXP   64
#define M_CTA  128
#define NCH    32           // k-chunks of 64
#define NSTG   4
#define NTHREADS 384

// stage: A-h0 [0,16K) | A-h1 [16K,32K) | W-w0 [32K,40K) | W-w1 [40K,48K)
#define AB       16384
#define WB       8192
#define STGSZ    49152
#define STG(s)   (1024 + (s) * STGSZ)
#define SMEM_TOTAL (1024 + NSTG * STGSZ)   // 197632
#define LG_OFF   1024
#define LGS      65
#define SW16(row, c) ((row) * 128 + ((((c) ^ ((row) & 7))) << 4))

// W fp16 splits: w0 = fp16(w), w1 = fp16((w - w0) * 2048)
__device__ __align__(16) __half w0g[NEXP * D_DIM];
__device__ __align__(16) __half w1g[NEXP * D_DIM];

__global__ void wconv(const float* __restrict__ W) {
    int i = blockIdx.x * blockDim.x + threadIdx.x;
    float w = W[i];
    __half h0 = __float2half_rn(w);
    float  r  = w - __half2float(h0);
    w0g[i] = h0;
    w1g[i] = __float2half_rn(r * 2048.0f);
}

// ---------------- asm helpers ----------------
__device__ __forceinline__ uint32_t smem_u32(const void* p) {
    uint32_t a;
    asm("{ .reg .u64 t; cvta.to.shared.u64 t, %1; cvt.u32.u64 %0, t; }"
        : "=r"(a) : "l"(p));
    return a;
}
__device__ __forceinline__ void ldsm4(uint32_t* r, uint32_t addr) {
    asm volatile("ldmatrix.sync.aligned.m8n8.x4.shared.b16 {%0,%1,%2,%3}, [%4];"
                 : "=r"(r[0]), "=r"(r[1]), "=r"(r[2]), "=r"(r[3]) : "r"(addr));
}
__device__ __forceinline__ void mma16816(float* d, const uint32_t* a, const uint32_t* b) {
    asm volatile("mma.sync.aligned.m16n8k16.row.col.f32.f16.f16.f32 "
                 "{%0,%1,%2,%3}, {%4,%5,%6,%7}, {%8,%9}, {%0,%1,%2,%3};"
                 : "+f"(d[0]), "+f"(d[1]), "+f"(d[2]), "+f"(d[3])
                 : "r"(a[0]), "r"(a[1]), "r"(a[2]), "r"(a[3]), "r"(b[0]), "r"(b[1]));
}
__device__ __forceinline__ void cp16(uint32_t saddr, const void* gaddr) {
    asm volatile("cp.async.cg.shared.global [%0], [%1], 16;" :: "r"(saddr), "l"(gaddr));
}
#define MBAR_INIT(a, c) \
    asm volatile("mbarrier.init.shared.b64 [%0], %1;" :: "r"(a), "r"(c) : "memory")
#define MBAR_ARRIVE(a) \
    asm volatile("mbarrier.arrive.shared.b64 _, [%0];" :: "r"(a) : "memory")
// .noinc is load-bearing (default raises pend-count -> deadlock)
#define CP_MBAR_ARRIVE(a) \
    asm volatile("cp.async.mbarrier.arrive.noinc.shared.b64 [%0];" :: "r"(a) : "memory")
#define MBAR_WAIT(addr, ph) do { \
    asm volatile("{\n\t.reg .pred P;\n\tWLP_%=:\n\t" \
        "mbarrier.try_wait.parity.acquire.cta.shared::cta.b64 P, [%0], %1, 0x989680;\n\t" \
        "@!P bra WLP_%=;\n\t}" :: "r"(addr), "r"(ph) : "memory"); \
} while (0)
#define STS128(addr, v) \
    asm volatile("st.shared.v4.b32 [%0], {%1,%2,%3,%4};" \
                 :: "r"(addr), "r"((v).x), "r"((v).y), "r"((v).z), "r"((v).w) : "memory")

__device__ __forceinline__ uint32_t cvt2(float u, float v, uint32_t& h1) {
    __half2 a = __float22half2_rn(make_float2(u, v));
    float2 f  = __half22float2(a);
    __half2 r = __float22half2_rn(make_float2(u - f.x, v - f.y));
    h1 = *reinterpret_cast<uint32_t*>(&r);
    return *reinterpret_cast<uint32_t*>(&a);
}

// ---------------- main kernel ----------------
__global__ __launch_bounds__(NTHREADS)
void router_main(const float* __restrict__ x, const float* __restrict__ b,
                 float* __restrict__ out, int n_tokens)
{
    extern __shared__ __align__(1024) char smem[];
    const uint32_t sb = smem_u32(smem);
    const int tid  = threadIdx.x;
    const int lane = tid & 31;
    const int tok0 = blockIdx.x * M_CTA;

    // mbarriers: full[s] = sb+512+s*16, empty[s] = +8
    if (tid == 0) {
#pragma unroll
        for (int s = 0; s < NSTG; s++) {
            MBAR_INIT(sb + 512 + s * 16, 256);      // 128 STS-arr + 128 cp-arr
            MBAR_INIT(sb + 512 + s * 16 + 8, 256);  // 256 consumer arrivals
        }
    }
    if (tid < NEXP) reinterpret_cast<float*>(smem)[tid] = b[tid];
    __syncthreads();

    if (tid >= 256) {
        // ================= PRODUCER (warps 8-11, 128 threads) =================
        const int pt   = tid - 256;
        const int row  = pt;              // x row 0..127 (one full row per thread)
        const int wrow = pt & 63;         // W row
        const int wsp  = pt >> 6;         // W split 0/1
        const float4* xp = reinterpret_cast<const float4*>(x)
                           + (size_t)(tok0 + row) * (D_DIM / 4);
        const char* wg = reinterpret_cast<const char*>(wsp ? w1g : w0g)
                         + wrow * (D_DIM * 2);
        const uint32_t wdst_off = 32768 + wsp * WB;

        uint32_t asw[8], wsw[8];
#pragma unroll
        for (int q = 0; q < 8; q++) asw[q] = SW16(row, q);
#pragma unroll
        for (int c = 0; c < 8; c++) wsw[c] = SW16(wrow, c);

        float4 xv[16];
#pragma unroll
        for (int i = 0; i < 16; i++) xv[i] = xp[i];

        int s = 0, ph = 1;
        for (int ch = 0; ch < NCH; ch++) {
            const uint32_t fullb  = sb + 512 + s * 16;
            const uint32_t emptyb = fullb + 8;
            MBAR_WAIT(emptyb, ph);
            const uint32_t stg = sb + STG(s);

            // W chunk via cp.async first (independent of conversions)
#pragma unroll
            for (int c = 0; c < 8; c++)
                cp16(stg + wdst_off + wsw[c], wg + ch * 128 + c * 16);

            // x split: 64 floats -> 8x STS128 h0 + 8x STS128 h1
#pragma unroll
            for (int q = 0; q < 8; q++) {
                float4 a = xv[2 * q], c = xv[2 * q + 1];
                uint4 h0q, h1q;
                h0q.x = cvt2(a.x, a.y, h1q.x);
                h0q.y = cvt2(a.z, a.w, h1q.y);
                h0q.z = cvt2(c.x, c.y, h1q.z);
                h0q.w = cvt2(c.z, c.w, h1q.w);
                STS128(stg + asw[q], h0q);
                STS128(stg + AB + asw[q], h1q);
            }
            CP_MBAR_ARRIVE(fullb);
            MBAR_ARRIVE(fullb);

            if (ch + 1 < NCH) {
#pragma unroll
                for (int i = 0; i < 16; i++) xv[i] = xp[(ch + 1) * 16 + i];
            }
            if (++s == NSTG) { s = 0; ph ^= 1; }
        }
        return;
    }

    // ================= CONSUMER (warps 0-7) =================
    const int wid = tid >> 5;
    const int m0  = (wid & 3) * 32;      // 4 m-groups
    const int n0  = (wid >> 2) * 32;     // 2 n-groups

    float acc0[2][4][4], acc1[2][4][4];
#pragma unroll
    for (int mi = 0; mi < 2; mi++)
#pragma unroll
        for (int ng = 0; ng < 4; ng++)
#pragma unroll
            for (int q = 0; q < 4; q++) { acc0[mi][ng][q] = 0.f; acc1[mi][ng][q] = 0.f; }

    const int rowA  = m0 + (lane & 15);
    const int cAoff = lane >> 4;
    const int rowB  = n0 + (lane & 7) + ((lane >> 4) << 3);
    const int cBoff = (lane >> 3) & 1;

    int s = 0, ph = 0;
    for (int ch = 0; ch < NCH; ch++) {
        const uint32_t fullb  = sb + 512 + s * 16;
        const uint32_t emptyb = fullb + 8;
        MBAR_WAIT(fullb, ph);
        const uint32_t stg = sb + STG(s);

#pragma unroll
        for (int kk = 0; kk < 4; kk++) {
            uint32_t a0f[2][4], a1f[2][4], b0f[2][4], b1f[2][4];
            const int cA = kk * 2 + cAoff;
            const int cB = kk * 2 + cBoff;
#pragma unroll
            for (int mi = 0; mi < 2; mi++) {
                uint32_t ad = stg + SW16(rowA + mi * 16, cA);
                ldsm4(a0f[mi], ad);
                ldsm4(a1f[mi], ad + AB);
            }
#pragma unroll
            for (int ni2 = 0; ni2 < 2; ni2++) {
                uint32_t bd = stg + 32768 + SW16(rowB + ni2 * 16, cB);
                ldsm4(b0f[ni2], bd);
                ldsm4(b1f[ni2], bd + WB);
            }
#pragma unroll
            for (int mi = 0; mi < 2; mi++) {
#pragma unroll
                for (int ng = 0; ng < 4; ng++) {
                    const uint32_t* B0 = &b0f[ng >> 1][(ng & 1) * 2];
                    const uint32_t* B1 = &b1f[ng >> 1][(ng & 1) * 2];
                    mma16816(acc0[mi][ng], a0f[mi], B0);
                    mma16816(acc0[mi][ng], a1f[mi], B0);
                    mma16816(acc1[mi][ng], a0f[mi], B1);
                }
            }
        }
        MBAR_ARRIVE(emptyb);
        if (++s == NSTG) { s = 0; ph ^= 1; }
    }

    // All consumers done reading stage 0 before logits overwrite it.
    asm volatile("bar.sync 1, 256;" ::: "memory");

    // ---- epilogue: combine splits -> logits smem ----
    float* lg = reinterpret_cast<float*>(smem + LG_OFF);
    const float S = 4.8828125e-4f;  // 2^-11
#pragma unroll
    for (int mi = 0; mi < 2; mi++) {
#pragma unroll
        for (int ng = 0; ng < 4; ng++) {
            int row = m0 + mi * 16 + (lane >> 2);
            int col = n0 + ng * 8 + 2 * (lane & 3);
            lg[row * LGS + col]           = acc0[mi][ng][0] + S * acc1[mi][ng][0];
            lg[row * LGS + col + 1]       = acc0[mi][ng][1] + S * acc1[mi][ng][1];
            lg[(row + 8) * LGS + col]     = acc0[mi][ng][2] + S * acc1[mi][ng][2];
            lg[(row + 8) * LGS + col + 1] = acc0[mi][ng][3] + S * acc1[mi][ng][3];
        }
    }
    asm volatile("bar.sync 1, 256;" ::: "memory");

    // ---- top-2 + softmax, one thread per token ----
    if (tid < M_CTA) {
        const float* row = &lg[tid * LGS];
        const float* bs  = reinterpret_cast<const float*>(smem);
        float v1 = -3.402823466e+38f, v2 = -3.402823466e+38f;
        int i1 = 0, i2 = 0;
#pragma unroll
        for (int e = 0; e < NEXP; e++) {
            float v = row[e] + bs[e];
            if (v > v1)      { v2 = v1; i2 = i1; v1 = v; i1 = e; }
            else if (v > v2) { v2 = v;  i2 = e; }
        }
        float e2  = expf(v2 - v1);
        float inv = 1.0f / (1.0f + e2);
        const int g = tok0 + tid;
        out[2 * g + 0] = inv;
        out[2 * g + 1] = e2 * inv;
        out[2 * n_tokens + 2 * g + 0] = (float)i1;
        out[2 * n_tokens + 2 * g + 1] = (float)i2;
    }
}

// ---------------- launch ----------------
extern "C" void kernel_launch(void* const* d_in, const int* in_sizes, int n_in,
                              void* d_out, int out_size)
{
    const float* x = (const float*)d_in[0];
    const float* W = (const float*)d_in[1];
    const float* b = (const float*)d_in[2];
    float* out = (float*)d_out;

    const int n_tokens = in_sizes[0] / D_DIM;   // 16384
    const int grid = n_tokens / M_CTA;          // 128

    cudaFuncSetAttribute(router_main, cudaFuncAttributeMaxDynamicSharedMemorySize, SMEM_TOTAL);

    wconv<<<NEXP * D_DIM / 256, 256>>>(W);
    router_main<<<grid, NTHREADS, SMEM_TOTAL>>>(x, b, out, n_tokens);
}